// round 9
// baseline (speedup 1.0000x reference)
#include <cuda_runtime.h>
#include <cuda_bf16.h>
#include <cstdint>
#include <math.h>

#define NXC 49152
#define NYC 50000
#define NT_Y 391
#define NY_PAD (NT_Y*128)          // 50048
#define CDIM 128
#define KTOP 10
#define DEPTH 12
#define NCAND 96                   // 2 splits * 4 threads * 12
#define NXK (NXC*KTOP)
#define INV_TAU 20.0f

#define MTILES (NXC/64)            // 768
#define SPLIT_T 196                // split0: [0,196), split1: [196,391)

// gemm smem: A 16KB @0, B0 32KB @16384, B1 32KB @49152
#define SM_B0 16384
#define SM_B1 49152
#define SM_TOTAL 81920

// ---------------- device scratch ----------------
__device__ float g_x32[NXC*CDIM];      // normalized x, row-major (exact fp32)
__device__ float g_y32[NY_PAD*CDIM];   // normalized y, row-major, zero-padded
__device__ uint4 g_xA[MTILES*1024];    // A fragment images: 16KB per 64-row tile
__device__ uint4 g_yB[NT_Y*2048];      // B fragment images: 32KB per 128-col tile
__device__ int   g_candI[NXC*NCAND];   // candidate cols per row

// ---------------- helpers ----------------
__device__ __forceinline__ unsigned bf2(float a, float b) {
    __nv_bfloat162 h = __floats2bfloat162_rn(a, b);   // .x = low half
    return *(unsigned*)&h;
}
__device__ __forceinline__ void mma_bf16(float (&c)[4], const uint4& a, unsigned b0, unsigned b1) {
    asm volatile(
        "mma.sync.aligned.m16n8k16.row.col.f32.bf16.bf16.f32 "
        "{%0,%1,%2,%3}, {%4,%5,%6,%7}, {%8,%9}, {%0,%1,%2,%3};"
        : "+f"(c[0]), "+f"(c[1]), "+f"(c[2]), "+f"(c[3])
        : "r"(a.x), "r"(a.y), "r"(a.z), "r"(a.w), "r"(b0), "r"(b1));
}
__device__ __forceinline__ void insert12(float (&tv)[12], int (&ti)[12], float v, int j) {
    tv[11] = v; ti[11] = j;
#pragma unroll
    for (int s = 11; s > 0; --s) {
        bool sw = (tv[s] > tv[s-1]) || (tv[s] == tv[s-1] && ti[s] < ti[s-1]);
        if (sw) {
            float fv = tv[s]; tv[s] = tv[s-1]; tv[s-1] = fv;
            int   fi = ti[s]; ti[s] = ti[s-1]; ti[s-1] = fi;
        }
    }
}
__device__ __forceinline__ void insert10(float (&tv)[10], int (&ti)[10], float v, int j) {
    tv[9] = v; ti[9] = j;
#pragma unroll
    for (int s = 9; s > 0; --s) {
        bool sw = (tv[s] > tv[s-1]) || (tv[s] == tv[s-1] && ti[s] < ti[s-1]);
        if (sw) {
            float fv = tv[s]; tv[s] = tv[s-1]; tv[s-1] = fv;
            int   fi = ti[s]; ti[s] = ti[s-1]; ti[s-1] = fi;
        }
    }
}

// ---------------- normalize (EXACT same arithmetic as the passing chain) ----------------
__global__ void norm_x_kernel(const float* __restrict__ in) {
    int warp = (blockIdx.x * blockDim.x + threadIdx.x) >> 5;
    int lane = threadIdx.x & 31;
    if (warp >= NXC) return;
    float4 v = *(const float4*)&in[warp * CDIM + lane * 4];
    float ss = v.x*v.x + v.y*v.y + v.z*v.z + v.w*v.w;
#pragma unroll
    for (int o = 16; o > 0; o >>= 1) ss += __shfl_xor_sync(0xffffffffu, ss, o);
    float inv = 1.0f / fmaxf(sqrtf(ss), 1e-12f);
    *(float4*)&g_x32[warp * CDIM + lane * 4] = make_float4(v.x*inv, v.y*inv, v.z*inv, v.w*inv);
}
__global__ void norm_y_kernel(const float* __restrict__ in) {
    int warp = (blockIdx.x * blockDim.x + threadIdx.x) >> 5;
    int lane = threadIdx.x & 31;
    if (warp >= NY_PAD) return;
    if (warp >= NYC) {
        *(float4*)&g_y32[warp * CDIM + lane * 4] = make_float4(0.f, 0.f, 0.f, 0.f);
        return;
    }
    float4 v = *(const float4*)&in[warp * CDIM + lane * 4];
    float ss = v.x*v.x + v.y*v.y + v.z*v.z + v.w*v.w;
#pragma unroll
    for (int o = 16; o > 0; o >>= 1) ss += __shfl_xor_sync(0xffffffffu, ss, o);
    float inv = 1.0f / fmaxf(sqrtf(ss), 1e-12f);
    *(float4*)&g_y32[warp * CDIM + lane * 4] = make_float4(v.x*inv, v.y*inv, v.z*inv, v.w*inv);
}

// ---------------- fragment packing ----------------
// A image per 64-row mtile: uint4 index i = mt*1024 + (f*8 + k16)*32 + lane
//   -> lane = i&31, k16 = (i>>5)&7, f = (i>>8)&3, mt = i>>10   (FIXED decomposition)
// lane: g=lane>>2, t=lane&3; rows (mt*64+f*16+g, +8); k0 = k16*16 + t*2
__global__ void pack_x_frag() {
    int i = blockIdx.x * blockDim.x + threadIdx.x;
    if (i >= MTILES * 1024) return;
    int lane = i & 31;
    int k16  = (i >> 5) & 7;
    int f    = (i >> 8) & 3;
    int mt   = i >> 10;
    int g = lane >> 2, t = lane & 3;
    int r = mt * 64 + f * 16 + g;
    int k0 = k16 * 16 + t * 2;
    uint4 a;
    a.x = bf2(g_x32[r * CDIM + k0],           g_x32[r * CDIM + k0 + 1]);
    a.y = bf2(g_x32[(r + 8) * CDIM + k0],     g_x32[(r + 8) * CDIM + k0 + 1]);
    a.z = bf2(g_x32[r * CDIM + k0 + 8],       g_x32[r * CDIM + k0 + 9]);
    a.w = bf2(g_x32[(r + 8) * CDIM + k0 + 8], g_x32[(r + 8) * CDIM + k0 + 9]);
    g_xA[i] = a;
}
// B image per 128-col ytile: uint4 index (yt*2048 + (k16*8 + p)*32 + lane)
// uint4 = {b0,b1 of n-frag 2p ; b0,b1 of n-frag 2p+1}; n = frag*8 + g; k0 = k16*16 + t*2
__global__ void pack_y_frag() {
    int i = blockIdx.x * blockDim.x + threadIdx.x;
    if (i >= NT_Y * 2048) return;
    int lane = i & 31, p = (i >> 5) & 7, k16 = (i >> 8) & 7, yt = i >> 11;
    int g = lane >> 2, t = lane & 3;
    int ce = yt * 128 + p * 16 + g;        // even n-frag column
    int co = ce + 8;                       // odd n-frag column
    int k0 = k16 * 16 + t * 2;
    uint4 b;
    b.x = bf2(g_y32[ce * CDIM + k0],     g_y32[ce * CDIM + k0 + 1]);
    b.y = bf2(g_y32[ce * CDIM + k0 + 8], g_y32[ce * CDIM + k0 + 9]);
    b.z = bf2(g_y32[co * CDIM + k0],     g_y32[co * CDIM + k0 + 1]);
    b.w = bf2(g_y32[co * CDIM + k0 + 8], g_y32[co * CDIM + k0 + 9]);
    g_yB[i] = b;
}

// ---------------- cp.async helpers (128 threads) ----------------
__device__ __forceinline__ void cp_B(char* dst_sm, int yt, int tid) {
    const char* src = (const char*)(g_yB + (size_t)yt * 2048);
#pragma unroll
    for (int i = 0; i < 16; i++) {
        int off = (tid + 128 * i) * 16;
        unsigned s = (unsigned)__cvta_generic_to_shared(dst_sm + off);
        asm volatile("cp.async.cg.shared.global [%0], [%1], 16;" :: "r"(s), "l"(src + off));
    }
    asm volatile("cp.async.commit_group;" ::: "memory");
}
__device__ __forceinline__ void cp_A(char* dst_sm, int mt, int tid) {
    const char* src = (const char*)(g_xA + (size_t)mt * 1024);
#pragma unroll
    for (int i = 0; i < 8; i++) {
        int off = (tid + 128 * i) * 16;
        unsigned s = (unsigned)__cvta_generic_to_shared(dst_sm + off);
        asm volatile("cp.async.cg.shared.global [%0], [%1], 16;" :: "r"(s), "l"(src + off));
    }
    asm volatile("cp.async.commit_group;" ::: "memory");
}

// ---------------- bf16 mma GEMM + in-register streaming top-12 ----------------
__global__ __launch_bounds__(128, 2) void gemm_topk_kernel() {
    extern __shared__ char sm[];
    const int tid  = threadIdx.x;
    const int w    = tid >> 5;
    const int lane = tid & 31;
    const int g    = lane >> 2;
    const int t4   = lane & 3;
    const int mtile = blockIdx.x;
    const int split = blockIdx.y;
    const int t_lo = split * SPLIT_T;
    const int t_hi = split ? NT_Y : SPLIT_T;

    cp_A(sm, mtile, tid);
    cp_B(sm + SM_B0, t_lo, tid);

    const uint4* AsW = (const uint4*)sm + w * 8 * 32;   // this warp's m-frag, 8 k16 slabs

    float tvA[12], tvB[12]; int tiA[12], tiB[12];
#pragma unroll
    for (int q = 0; q < 12; q++) {
        tvA[q] = tvB[q] = -__int_as_float(0x7f800000);
        tiA[q] = tiB[q] = 0x7fffffff;
    }

    for (int t = t_lo; t < t_hi; t++) {
        if (t + 1 < t_hi) {
            cp_B(sm + (((t + 1) & 1) ? SM_B1 : SM_B0), t + 1, tid);
            asm volatile("cp.async.wait_group 1;" ::: "memory");
        } else {
            asm volatile("cp.async.wait_group 0;" ::: "memory");
        }
        __syncthreads();

        const uint4* Bs = (const uint4*)(sm + ((t & 1) ? SM_B1 : SM_B0));

        float acc[16][4];
#pragma unroll
        for (int nf = 0; nf < 16; nf++)
#pragma unroll
            for (int p = 0; p < 4; p++) acc[nf][p] = 0.0f;

#pragma unroll
        for (int k16 = 0; k16 < 8; k16++) {
            uint4 a = AsW[k16 * 32 + lane];
            const uint4* Bk = Bs + k16 * 8 * 32;
#pragma unroll
            for (int p = 0; p < 8; p++) {
                uint4 bb = Bk[p * 32 + lane];
                mma_bf16(acc[2*p],     a, bb.x, bb.y);
                mma_bf16(acc[2*p + 1], a, bb.z, bb.w);
            }
        }

        // scan accumulators: this thread owns rows (g, g+8), cols nf*8 + t4*2 + {0,1}
        int n0 = t * 128 + t4 * 2;
#pragma unroll
        for (int nf = 0; nf < 16; nf++) {
            int j0 = n0 + nf * 8;
            float v0 = acc[nf][0], v1 = acc[nf][1], v2 = acc[nf][2], v3 = acc[nf][3];
            if (v0 > tvA[11] && j0 < NYC)     insert12(tvA, tiA, v0, j0);
            if (v1 > tvA[11] && j0 + 1 < NYC) insert12(tvA, tiA, v1, j0 + 1);
            if (v2 > tvB[11] && j0 < NYC)     insert12(tvB, tiB, v2, j0);
            if (v3 > tvB[11] && j0 + 1 < NYC) insert12(tvB, tiB, v3, j0 + 1);
        }
        __syncthreads();   // all warps done with this B buffer before next-iter cp overwrites peer buffer
    }

    int mA = mtile * 64 + w * 16 + g;
    int mB = mA + 8;
    int base = split * 48 + t4 * 12;
#pragma unroll
    for (int q = 0; q < 12; q++) {
        g_candI[mA * NCAND + base + q] = tiA[q];
        g_candI[mB * NCAND + base + q] = tiB[q];
    }
}

// ---------------- exact fp32 rescore (bitwise-identical chain) + softmax + COO ----------------
__global__ __launch_bounds__(128) void rescore_kernel(float* __restrict__ out) {
    extern __shared__ float rs[];
    float* xrow  = rs;                        // 128
    float* yrows = rs + 128;                  // 96 * 129 (pitch 129 -> conflict-free)
    float* vals  = yrows + 96 * 129;          // 96
    int*   cols  = (int*)(vals + 96);         // 96

    const int m = blockIdx.x;
    const int tid = threadIdx.x;

    if (tid < 128) xrow[tid] = g_x32[m * CDIM + tid];
    if (tid < 96)  cols[tid] = g_candI[m * NCAND + tid];
    __syncthreads();

    for (int i = tid; i < 96 * 32; i += 128) {
        int c = i >> 5, p = i & 31;
        float4 v = *(const float4*)&g_y32[(size_t)cols[c] * CDIM + p * 4];
        float* dst = &yrows[c * 129 + p * 4];
        dst[0] = v.x; dst[1] = v.y; dst[2] = v.z; dst[3] = v.w;
    }
    __syncthreads();

    if (tid < 96) {
        float s = 0.0f;
        const float* yr = &yrows[tid * 129];
#pragma unroll 16
        for (int k = 0; k < 128; k++) s = fmaf(xrow[k], yr[k], s);
        vals[tid] = s;
    }
    __syncthreads();

    if (tid == 0) {
        float tv[10]; int tix[10];
#pragma unroll
        for (int q = 0; q < 10; q++) { tv[q] = -__int_as_float(0x7f800000); tix[q] = 0x7fffffff; }
        for (int c = 0; c < 96; c++) {
            float v = vals[c]; int j = cols[c];
            if (v > tv[9] || (v == tv[9] && j < tix[9])) insert10(tv, tix, v, j);
        }
        float mx = tv[0];
        float e[10], sum = 0.0f;
#pragma unroll
        for (int q = 0; q < 10; q++) { e[q] = expf((tv[q] - mx) * INV_TAU); sum += e[q]; }
        float inv = 1.0f / sum;
#pragma unroll
        for (int q = 0; q < 10; q++) {
            out[m * 10 + q]           = e[q] * inv;
            out[NXK + m * 10 + q]     = (float)m;
            out[2 * NXK + m * 10 + q] = (float)tix[q];
        }
    }
}

// ---------------- launch ----------------
extern "C" void kernel_launch(void* const* d_in, const int* in_sizes, int n_in,
                              void* d_out, int out_size) {
    const float* fx = (const float*)d_in[0];
    const float* fy = (const float*)d_in[1];
    if (n_in >= 2 && in_sizes[0] == NYC * CDIM && in_sizes[1] == NXC * CDIM) {
        const float* t = fx; fx = fy; fy = t;
    }
    float* outF = (float*)d_out;

    cudaFuncSetAttribute(gemm_topk_kernel,
                         cudaFuncAttributeMaxDynamicSharedMemorySize, SM_TOTAL);
    cudaFuncSetAttribute(rescore_kernel,
                         cudaFuncAttributeMaxDynamicSharedMemorySize, 50816);

    norm_x_kernel<<<NXC / 8, 256>>>(fx);
    norm_y_kernel<<<NY_PAD / 8, 256>>>(fy);
    pack_x_frag<<<(MTILES * 1024 + 255) / 256, 256>>>();
    pack_y_frag<<<(NT_Y * 2048 + 255) / 256, 256>>>();
    gemm_topk_kernel<<<dim3(MTILES, 2), 128, SM_TOTAL>>>();
    rescore_kernel<<<NXC, 128, 50816>>>(outF);
}

// round 11
// speedup vs baseline: 2.7746x; 2.7746x over previous
#include <cuda_runtime.h>
#include <cstdint>
#include <math.h>

#define NXC 49152
#define NYC 50000
#define NT_Y 392
#define NY_PAD (NT_Y*128)          // 50176 (padded, qy=0, sy=0)
#define CDIM 128
#define KTOP 10
#define DEPTH 12
#define NSPLIT 4
#define TILES_PER_SPLIT 98
#define NCAND 96                   // 4 splits * 2 halves * 12
#define NXK (NXC*KTOP)
#define INV_TAU 20.0f
#define MTILES (NXC/128)           // 384

// gemm smem byte offsets
#define SM_XQ   0                  // 16KB
#define SM_YQ0  16384              // 16KB
#define SM_YQ1  32768              // 16KB
#define SM_SY0  49152              // 512B
#define SM_SY1  49664              // 512B
#define SM_SB   50176              // 128*132*4 = 67584
#define SM_TOTAL 117760

// ---------------- device scratch ----------------
__device__ float g_x32[NXC*CDIM];      // normalized x, row-major (exact fp32)
__device__ float g_y32[NY_PAD*CDIM];   // normalized y, row-major, zero-padded
__device__ int   g_xq[MTILES*4096];    // int8x4 x images: [mt][c][m]  (16KB/tile)
__device__ int   g_yq[NT_Y*4096];      // int8x4 y images: [yt][c][j]  (16KB/tile)
__device__ float g_sy[NY_PAD];         // per-y-row quant scale (0 on pad)
__device__ int   g_candI[NXC*NCAND];   // candidate cols per row

// ---------------- helpers ----------------
__device__ __forceinline__ int dp4a(int a, int b, int c) {
    int d;
    asm("dp4a.s32.s32 %0, %1, %2, %3;" : "=r"(d) : "r"(a), "r"(b), "r"(c));
    return d;
}
__device__ __forceinline__ int q8(float v, float rs) {
    int q = __float2int_rn(v * rs);
    q = max(-127, min(127, q));
    return q & 255;
}
__device__ __forceinline__ void insert12(float (&tv)[12], int (&ti)[12], float v, int j) {
    tv[11] = v; ti[11] = j;
#pragma unroll
    for (int s = 11; s > 0; --s) {
        bool sw = (tv[s] > tv[s-1]) || (tv[s] == tv[s-1] && ti[s] < ti[s-1]);
        if (sw) {
            float fv = tv[s]; tv[s] = tv[s-1]; tv[s-1] = fv;
            int   fi = ti[s]; ti[s] = ti[s-1]; ti[s-1] = fi;
        }
    }
}
__device__ __forceinline__ void insert10(float (&tv)[10], int (&ti)[10], float v, int j) {
    tv[9] = v; ti[9] = j;
#pragma unroll
    for (int s = 9; s > 0; --s) {
        bool sw = (tv[s] > tv[s-1]) || (tv[s] == tv[s-1] && ti[s] < ti[s-1]);
        if (sw) {
            float fv = tv[s]; tv[s] = tv[s-1]; tv[s-1] = fv;
            int   fi = ti[s]; ti[s] = ti[s-1]; ti[s-1] = fi;
        }
    }
}

// ---------------- normalize (EXACT proven arithmetic) + fused int8 quant ----------------
__global__ void norm_x_kernel(const float* __restrict__ in) {
    int warp = (blockIdx.x * blockDim.x + threadIdx.x) >> 5;
    int lane = threadIdx.x & 31;
    if (warp >= NXC) return;
    float4 v = *(const float4*)&in[warp * CDIM + lane * 4];
    float ss = v.x*v.x + v.y*v.y + v.z*v.z + v.w*v.w;
#pragma unroll
    for (int o = 16; o > 0; o >>= 1) ss += __shfl_xor_sync(0xffffffffu, ss, o);
    float inv = 1.0f / fmaxf(sqrtf(ss), 1e-12f);
    float4 nv = make_float4(v.x*inv, v.y*inv, v.z*inv, v.w*inv);
    *(float4*)&g_x32[warp * CDIM + lane * 4] = nv;
    // quant
    float ma = fmaxf(fmaxf(fabsf(nv.x), fabsf(nv.y)), fmaxf(fabsf(nv.z), fabsf(nv.w)));
#pragma unroll
    for (int o = 16; o > 0; o >>= 1) ma = fmaxf(ma, __shfl_xor_sync(0xffffffffu, ma, o));
    float rs = (ma > 0.f) ? 127.0f / ma : 0.f;
    int packed = q8(nv.x, rs) | (q8(nv.y, rs) << 8) | (q8(nv.z, rs) << 16) | (q8(nv.w, rs) << 24);
    g_xq[(warp >> 7) * 4096 + lane * 128 + (warp & 127)] = packed;
}
__global__ void norm_y_kernel(const float* __restrict__ in) {
    int warp = (blockIdx.x * blockDim.x + threadIdx.x) >> 5;
    int lane = threadIdx.x & 31;
    if (warp >= NY_PAD) return;
    if (warp >= NYC) {
        *(float4*)&g_y32[warp * CDIM + lane * 4] = make_float4(0.f, 0.f, 0.f, 0.f);
        g_yq[(warp >> 7) * 4096 + lane * 128 + (warp & 127)] = 0;
        if (lane == 0) g_sy[warp] = 0.f;
        return;
    }
    float4 v = *(const float4*)&in[warp * CDIM + lane * 4];
    float ss = v.x*v.x + v.y*v.y + v.z*v.z + v.w*v.w;
#pragma unroll
    for (int o = 16; o > 0; o >>= 1) ss += __shfl_xor_sync(0xffffffffu, ss, o);
    float inv = 1.0f / fmaxf(sqrtf(ss), 1e-12f);
    float4 nv = make_float4(v.x*inv, v.y*inv, v.z*inv, v.w*inv);
    *(float4*)&g_y32[warp * CDIM + lane * 4] = nv;
    float ma = fmaxf(fmaxf(fabsf(nv.x), fabsf(nv.y)), fmaxf(fabsf(nv.z), fabsf(nv.w)));
#pragma unroll
    for (int o = 16; o > 0; o >>= 1) ma = fmaxf(ma, __shfl_xor_sync(0xffffffffu, ma, o));
    float rs = (ma > 0.f) ? 127.0f / ma : 0.f;
    int packed = q8(nv.x, rs) | (q8(nv.y, rs) << 8) | (q8(nv.z, rs) << 16) | (q8(nv.w, rs) << 24);
    g_yq[(warp >> 7) * 4096 + lane * 128 + (warp & 127)] = packed;
    if (lane == 0) g_sy[warp] = ma / 127.0f;
}

// ---------------- cp.async tile loaders (256 threads) ----------------
__device__ __forceinline__ void cp_xtile(char* sm, int mt, int tid) {
    const char* src = (const char*)(g_xq + (size_t)mt * 4096);
#pragma unroll
    for (int i = 0; i < 4; i++) {
        int off = (tid + 256 * i) * 16;
        unsigned s = (unsigned)__cvta_generic_to_shared(sm + SM_XQ + off);
        asm volatile("cp.async.cg.shared.global [%0], [%1], 16;" :: "r"(s), "l"(src + off));
    }
    asm volatile("cp.async.commit_group;" ::: "memory");
}
__device__ __forceinline__ void cp_ytile(char* sm, int buf, int yt, int tid) {
    const char* src = (const char*)(g_yq + (size_t)yt * 4096);
    char* dstq = sm + (buf ? SM_YQ1 : SM_YQ0);
#pragma unroll
    for (int i = 0; i < 4; i++) {
        int off = (tid + 256 * i) * 16;
        unsigned s = (unsigned)__cvta_generic_to_shared(dstq + off);
        asm volatile("cp.async.cg.shared.global [%0], [%1], 16;" :: "r"(s), "l"(src + off));
    }
    if (tid < 32) {
        const char* ssrc = (const char*)(g_sy + (size_t)yt * 128);
        unsigned s = (unsigned)__cvta_generic_to_shared(sm + (buf ? SM_SY1 : SM_SY0) + tid * 16);
        asm volatile("cp.async.cg.shared.global [%0], [%1], 16;" :: "r"(s), "l"(ssrc + tid * 16));
    }
    asm volatile("cp.async.commit_group;" ::: "memory");
}

// ---------------- dp4a int8 GEMM + proven spill-scan top-12 ----------------
__global__ __launch_bounds__(256) void gemm_topk_kernel() {
    extern __shared__ char sm[];
    const int* xq = (const int*)(sm + SM_XQ);
    float* sb = (float*)(sm + SM_SB);

    const int tid  = threadIdx.x;
    const int ty   = tid >> 4;       // 16 row-groups of 8
    const int tx   = tid & 15;       // 16 col-groups of 8
    const int row  = tid & 127;
    const int half = tid >> 7;
    const int lane = tid & 31;
    const int mtile = blockIdx.x;
    const int split = blockIdx.y;
    const int t_lo = split * TILES_PER_SPLIT;
    const int t_hi = t_lo + TILES_PER_SPLIT;

    cp_xtile(sm, mtile, tid);
    cp_ytile(sm, 0, t_lo, tid);

    float tv[12]; int ti[12];
#pragma unroll
    for (int q = 0; q < 12; q++) { tv[q] = -__int_as_float(0x7f800000); ti[q] = 0x7fffffff; }

    const int* xa = xq + ty * 8;

    for (int t = t_lo; t < t_hi; t++) {
        asm volatile("cp.async.wait_group 0;" ::: "memory");
        __syncthreads();                       // orders prev-iter scan before this spill too
        if (t + 1 < t_hi) cp_ytile(sm, (t + 1) & 1, t + 1, tid);

        const int*   yq  = (const int*)(sm + ((t & 1) ? SM_YQ1 : SM_YQ0));
        const float* sys = (const float*)(sm + ((t & 1) ? SM_SY1 : SM_SY0));
        const int* yb = yq + tx * 8;

        int acc[8][8];
#pragma unroll
        for (int i = 0; i < 8; i++)
#pragma unroll
            for (int j = 0; j < 8; j++) acc[i][j] = 0;

#pragma unroll 8
        for (int c = 0; c < 32; c++) {
            int4 a0 = *(const int4*)(xa + c * 128);
            int4 a1 = *(const int4*)(xa + c * 128 + 4);
            int4 b0 = *(const int4*)(yb + c * 128);
            int4 b1 = *(const int4*)(yb + c * 128 + 4);
            int av[8] = {a0.x, a0.y, a0.z, a0.w, a1.x, a1.y, a1.z, a1.w};
            int bv[8] = {b0.x, b0.y, b0.z, b0.w, b1.x, b1.y, b1.z, b1.w};
#pragma unroll
            for (int i = 0; i < 8; i++)
#pragma unroll
                for (int j = 0; j < 8; j++)
                    acc[i][j] = dp4a(av[i], bv[j], acc[i][j]);
        }

        // spill scaled floats (per-col scale preserves cross-col ordering)
        float sc[8];
#pragma unroll
        for (int j = 0; j < 8; j++) sc[j] = sys[tx * 8 + j];
#pragma unroll
        for (int i = 0; i < 8; i++) {
            float f[8];
#pragma unroll
            for (int j = 0; j < 8; j++) f[j] = __int2float_rn(acc[i][j]) * sc[j];
            float4* d = (float4*)&sb[(ty * 8 + i) * 132 + tx * 8];
            d[0] = make_float4(f[0], f[1], f[2], f[3]);
            d[1] = make_float4(f[4], f[5], f[6], f[7]);
        }
        __syncthreads();

        // proven skewed scan: 2 threads per row, 64 cols each
        int n0 = t * 128;
#pragma unroll 4
        for (int s = 0; s < 64; s++) {
            int col = (half << 6) + ((s + lane) & 63);
            float v = sb[row * 132 + col];
            int j = n0 + col;
            if (j < NYC && v > tv[11]) insert12(tv, ti, v, j);
        }
        // next-iter top sync orders this scan before next spill
    }

    int m = mtile * 128 + row;
#pragma unroll
    for (int q = 0; q < 12; q++)
        g_candI[m * NCAND + (split * 2 + half) * DEPTH + q] = ti[q];
}

// ---------------- exact fp32 rescore (bitwise-identical chain) + softmax + COO ----------------
__global__ __launch_bounds__(128) void rescore_kernel(float* __restrict__ out) {
    extern __shared__ float rs[];
    float* xrow  = rs;                        // 128
    float* yrows = rs + 128;                  // 96 * 129 (pitch 129 -> conflict-free)
    float* vals  = yrows + 96 * 129;          // 96
    int*   cols  = (int*)(vals + 96);         // 96

    const int m = blockIdx.x;
    const int tid = threadIdx.x;

    if (tid < 128) xrow[tid] = g_x32[m * CDIM + tid];
    if (tid < 96)  cols[tid] = g_candI[m * NCAND + tid];
    __syncthreads();

    for (int i = tid; i < 96 * 32; i += 128) {
        int c = i >> 5, p = i & 31;
        float4 v = *(const float4*)&g_y32[(size_t)cols[c] * CDIM + p * 4];
        float* dst = &yrows[c * 129 + p * 4];
        dst[0] = v.x; dst[1] = v.y; dst[2] = v.z; dst[3] = v.w;
    }
    __syncthreads();

    if (tid < 96) {
        float s = 0.0f;
        const float* yr = &yrows[tid * 129];
#pragma unroll 16
        for (int k = 0; k < 128; k++) s = fmaf(xrow[k], yr[k], s);
        vals[tid] = s;
    }
    __syncthreads();

    if (tid == 0) {
        float tv[10]; int tix[10];
#pragma unroll
        for (int q = 0; q < 10; q++) { tv[q] = -__int_as_float(0x7f800000); tix[q] = 0x7fffffff; }
        for (int c = 0; c < 96; c++) {
            float v = vals[c]; int j = cols[c];
            if (v > tv[9] || (v == tv[9] && j < tix[9])) insert10(tv, tix, v, j);
        }
        float mx = tv[0];
        float e[10], sum = 0.0f;
#pragma unroll
        for (int q = 0; q < 10; q++) { e[q] = expf((tv[q] - mx) * INV_TAU); sum += e[q]; }
        float inv = 1.0f / sum;
#pragma unroll
        for (int q = 0; q < 10; q++) {
            out[m * 10 + q]           = e[q] * inv;
            out[NXK + m * 10 + q]     = (float)m;
            out[2 * NXK + m * 10 + q] = (float)tix[q];
        }
    }
}

// ---------------- launch ----------------
extern "C" void kernel_launch(void* const* d_in, const int* in_sizes, int n_in,
                              void* d_out, int out_size) {
    const float* fx = (const float*)d_in[0];
    const float* fy = (const float*)d_in[1];
    if (n_in >= 2 && in_sizes[0] == NYC * CDIM && in_sizes[1] == NXC * CDIM) {
        const float* t = fx; fx = fy; fy = t;
    }
    float* outF = (float*)d_out;

    cudaFuncSetAttribute(gemm_topk_kernel,
                         cudaFuncAttributeMaxDynamicSharedMemorySize, SM_TOTAL);
    cudaFuncSetAttribute(rescore_kernel,
                         cudaFuncAttributeMaxDynamicSharedMemorySize, 50816);

    norm_x_kernel<<<NXC / 8, 256>>>(fx);
    norm_y_kernel<<<NY_PAD / 8, 256>>>(fy);
    gemm_topk_kernel<<<dim3(MTILES, NSPLIT), 256, SM_TOTAL>>>();
    rescore_kernel<<<NXC, 128, 50816>>>(outF);
}